// round 16
// baseline (speedup 1.0000x reference)
#include <cuda_runtime.h>
#include <cstdint>

#define NNODES 50000
#define DIM 64
#define CAP 128          // per-node bucket capacity; deg ~ Binomial(8e5, 2e-5), mean 16
#define EPS_MSG 1e-7f
#define LOG2E 1.4426950408889634f

// Static scratch
__device__ int   g_cnt[NNODES];
__device__ int   g_slot[NNODES * CAP];   // per-node src lists (node indices)
__device__ float g_agg[NNODES * DIM];    // aggregated rows
__device__ int   g_is64;                 // edge_index dtype flag

// ---------------------------------------------------------------------------
// init: zero counters; warp 0 of block 0 probes edge_index dtype in parallel.
// int64 data: all values in [0,N). int32 read as int64: lo + hi*2^32, out of
// range unless hi==0 (~1/N per probe; 32 parallel probes => ~impossible).
// ---------------------------------------------------------------------------
__global__ void init_kernel(const void* __restrict__ ei, int E, int N) {
    int i = blockIdx.x * blockDim.x + threadIdx.x;
    if (i < N) g_cnt[i] = 0;
    if (blockIdx.x == 0 && threadIdx.x < 32) {
        const long long* p = (const long long*)ei;
        int probes = (2 * E < 32) ? 2 * E : 32;
        int bad = 0;
        if ((int)threadIdx.x < probes) {
            long long v = p[threadIdx.x];
            bad = (v < 0 || v >= (long long)N);
        }
        unsigned m = __ballot_sync(0xFFFFFFFFu, bad);
        if (threadIdx.x == 0) g_is64 = (m == 0u) ? 1 : 0;
    }
}

// ---------------------------------------------------------------------------
// bucket build: claim a slot in dst's list, record src. cnt = final degree.
// 2 edges per thread, vectorized index loads.
// ---------------------------------------------------------------------------
__global__ void build_kernel(const void* __restrict__ ei, int E, int N) {
    int t = blockIdx.x * blockDim.x + threadIdx.x;
    int e = t * 2;
    if (e >= E) return;
    int d0, s0, d1, s1;
    bool two = (e + 1 < E);
    if (g_is64) {
        const long long* p = (const long long*)ei;
        if (two) {
            longlong2 dv = __ldg(reinterpret_cast<const longlong2*>(p + e));
            longlong2 sv = __ldg(reinterpret_cast<const longlong2*>(p + (long long)E + e));
            d0 = (int)dv.x; d1 = (int)dv.y;
            s0 = (int)sv.x; s1 = (int)sv.y;
        } else {
            d0 = (int)p[e]; s0 = (int)p[(long long)E + e];
            d1 = -1; s1 = -1;
        }
    } else {
        const int* p = (const int*)ei;
        if (two) {
            int2 dv = __ldg(reinterpret_cast<const int2*>(p + e));
            int2 sv = __ldg(reinterpret_cast<const int2*>(p + E + e));
            d0 = dv.x; d1 = dv.y;
            s0 = sv.x; s1 = sv.y;
        } else {
            d0 = p[e]; s0 = p[E + e];
            d1 = -1; s1 = -1;
        }
    }
    if ((unsigned)d0 < (unsigned)N && (unsigned)s0 < (unsigned)N) {
        int pos = atomicAdd(&g_cnt[d0], 1);
        if (pos < CAP) g_slot[d0 * CAP + pos] = s0;
    }
    if (two && (unsigned)d1 < (unsigned)N && (unsigned)s1 < (unsigned)N) {
        int pos = atomicAdd(&g_cnt[d1], 1);
        if (pos < CAP) g_slot[d1 * CAP + pos] = s1;
    }
}

// ---------------------------------------------------------------------------
// aggregate: one warp per node (6250 blocks, no grid-stride, no smem), lane
// owns 2 channels. Exact algebra (eps + common exp factor cancel):
//   agg_c = (Σ r·exp2(bl·r)) / (Σ exp2(bl·r)) + eps,  r = relu(x), bl = β·log2e
// ---------------------------------------------------------------------------
__global__ void __launch_bounds__(256) agg_kernel(const float* __restrict__ x,
                                                  const float* __restrict__ beta,
                                                  int N) {
    int warp = (int)((blockIdx.x * blockDim.x + threadIdx.x) >> 5);
    int lane = threadIdx.x & 31;
    if (warp >= N) return;

    int deg = g_cnt[warp];
    if (deg > CAP) deg = CAP;
    const float bl = __ldg(beta) * LOG2E;
    const int* slots = g_slot + (size_t)warp * CAP;

    float d0 = 0.f, d1 = 0.f, n0 = 0.f, n1 = 0.f;

    int i = 0;
    for (; i + 4 <= deg; i += 4) {
        int4 s = __ldg(reinterpret_cast<const int4*>(slots + i));  // broadcast, aligned
        float2 va = __ldg(reinterpret_cast<const float2*>(x + (size_t)s.x * DIM) + lane);
        float2 vb = __ldg(reinterpret_cast<const float2*>(x + (size_t)s.y * DIM) + lane);
        float2 vc = __ldg(reinterpret_cast<const float2*>(x + (size_t)s.z * DIM) + lane);
        float2 vd = __ldg(reinterpret_cast<const float2*>(x + (size_t)s.w * DIM) + lane);

#define ACC2(v)                                                   \
        {                                                         \
            float r0 = fmaxf((v).x, 0.f), r1 = fmaxf((v).y, 0.f); \
            float t0 = exp2f(bl * r0),    t1 = exp2f(bl * r1);    \
            d0 += t0; d1 += t1;                                   \
            n0 = fmaf(r0, t0, n0); n1 = fmaf(r1, t1, n1);         \
        }
        ACC2(va) ACC2(vb) ACC2(vc) ACC2(vd)
    }
    for (; i < deg; i++) {
        int s0 = __ldg(slots + i);
        float2 v = __ldg(reinterpret_cast<const float2*>(x + (size_t)s0 * DIM) + lane);
        ACC2(v)
    }
#undef ACC2

    float2 o;
    if (deg > 0) {
        o.x = n0 / d0 + EPS_MSG;   // d>0 guaranteed: exp2 > 0
        o.y = n1 / d1 + EPS_MSG;
    } else {
        o.x = 0.f; o.y = 0.f;      // empty segment -> agg = 0 (matches reference)
    }
    *(reinterpret_cast<float2*>(g_agg + (size_t)warp * DIM) + lane) = o;
}

// ---------------------------------------------------------------------------
// out = agg @ W^T + b. One warp per 4-node group. Group load = 4 COALESCED
// LDG.64 (lane grabs float2 of each row; one L2 round-trip, MLP=4), staged in
// per-warp smem. Inner loop is all-smem: 2 conflict-free W LDS.128 + 4
// broadcast agg LDS.128 + 32 FMA per kq. Per-group global loads: 64 -> 4.
// ---------------------------------------------------------------------------
__global__ void __launch_bounds__(256) out_kernel(const float* __restrict__ W,
                                                  const float* __restrict__ b,
                                                  float* __restrict__ out,
                                                  int N) {
    __shared__ __align__(16) float4 WA[16][32];      // WA[kq][l] = W[2l][4kq..]
    __shared__ __align__(16) float4 WB[16][32];      // WB[kq][l] = W[2l+1][4kq..]
    __shared__ __align__(16) float stage[8][4][DIM]; // 8 KB: [warp][row][chan]

    for (int i = threadIdx.x; i < 512; i += 256) {
        int kq = i >> 5, l = i & 31;
        WA[kq][l] = __ldg(reinterpret_cast<const float4*>(W + (size_t)(2 * l) * DIM + 4 * kq));
        WB[kq][l] = __ldg(reinterpret_cast<const float4*>(W + (size_t)(2 * l + 1) * DIM + 4 * kq));
    }
    __syncthreads();

    const int wid  = threadIdx.x >> 5;
    const int lane = threadIdx.x & 31;
    const float bc0 = __ldg(b + 2 * lane);
    const float bc1 = __ldg(b + 2 * lane + 1);
    const int gstride = gridDim.x * 8 * 4;

    for (int base = (blockIdx.x * 8 + wid) * 4; base < N; base += gstride) {
        const bool full = (base + 3 < N);   // N=50000 divisible by 4 -> always true here
        // 4 coalesced row loads (float2 per lane), one batched wave
        const float2* g2 = reinterpret_cast<const float2*>(g_agg) ;
        float2 t0 = __ldg(g2 + (size_t)(base + 0) * 32 + lane);
        float2 t1, t2, t3;
        if (full) {
            t1 = __ldg(g2 + (size_t)(base + 1) * 32 + lane);
            t2 = __ldg(g2 + (size_t)(base + 2) * 32 + lane);
            t3 = __ldg(g2 + (size_t)(base + 3) * 32 + lane);
        } else {
            t1 = make_float2(0.f, 0.f); t2 = t1; t3 = t1;
        }
        *reinterpret_cast<float2*>(&stage[wid][0][2 * lane]) = t0;
        *reinterpret_cast<float2*>(&stage[wid][1][2 * lane]) = t1;
        *reinterpret_cast<float2*>(&stage[wid][2][2 * lane]) = t2;
        *reinterpret_cast<float2*>(&stage[wid][3][2 * lane]) = t3;
        __syncwarp();

        float acc00 = bc0, acc01 = bc1;   // node 0: channels 2l, 2l+1
        float acc10 = bc0, acc11 = bc1;   // node 1
        float acc20 = bc0, acc21 = bc1;   // node 2
        float acc30 = bc0, acc31 = bc1;   // node 3

#pragma unroll
        for (int kq = 0; kq < 16; kq++) {
            float4 wa = WA[kq][lane];     // conflict-free, amortized over 4 nodes
            float4 wb = WB[kq][lane];
            float4 a0 = *reinterpret_cast<const float4*>(&stage[wid][0][4 * kq]); // broadcast
            float4 a1 = *reinterpret_cast<const float4*>(&stage[wid][1][4 * kq]);
            float4 a2 = *reinterpret_cast<const float4*>(&stage[wid][2][4 * kq]);
            float4 a3 = *reinterpret_cast<const float4*>(&stage[wid][3][4 * kq]);

            acc00 = fmaf(a0.x, wa.x, acc00); acc00 = fmaf(a0.y, wa.y, acc00);
            acc00 = fmaf(a0.z, wa.z, acc00); acc00 = fmaf(a0.w, wa.w, acc00);
            acc01 = fmaf(a0.x, wb.x, acc01); acc01 = fmaf(a0.y, wb.y, acc01);
            acc01 = fmaf(a0.z, wb.z, acc01); acc01 = fmaf(a0.w, wb.w, acc01);

            acc10 = fmaf(a1.x, wa.x, acc10); acc10 = fmaf(a1.y, wa.y, acc10);
            acc10 = fmaf(a1.z, wa.z, acc10); acc10 = fmaf(a1.w, wa.w, acc10);
            acc11 = fmaf(a1.x, wb.x, acc11); acc11 = fmaf(a1.y, wb.y, acc11);
            acc11 = fmaf(a1.z, wb.z, acc11); acc11 = fmaf(a1.w, wb.w, acc11);

            acc20 = fmaf(a2.x, wa.x, acc20); acc20 = fmaf(a2.y, wa.y, acc20);
            acc20 = fmaf(a2.z, wa.z, acc20); acc20 = fmaf(a2.w, wa.w, acc20);
            acc21 = fmaf(a2.x, wb.x, acc21); acc21 = fmaf(a2.y, wb.y, acc21);
            acc21 = fmaf(a2.z, wb.z, acc21); acc21 = fmaf(a2.w, wb.w, acc21);

            acc30 = fmaf(a3.x, wa.x, acc30); acc30 = fmaf(a3.y, wa.y, acc30);
            acc30 = fmaf(a3.z, wa.z, acc30); acc30 = fmaf(a3.w, wa.w, acc30);
            acc31 = fmaf(a3.x, wb.x, acc31); acc31 = fmaf(a3.y, wb.y, acc31);
            acc31 = fmaf(a3.z, wb.z, acc31); acc31 = fmaf(a3.w, wb.w, acc31);
        }

        float2 ov;
        ov.x = acc00; ov.y = acc01;
        *(reinterpret_cast<float2*>(out + (size_t)(base + 0) * DIM) + lane) = ov;
        if (full) {
            ov.x = acc10; ov.y = acc11;
            *(reinterpret_cast<float2*>(out + (size_t)(base + 1) * DIM) + lane) = ov;
            ov.x = acc20; ov.y = acc21;
            *(reinterpret_cast<float2*>(out + (size_t)(base + 2) * DIM) + lane) = ov;
            ov.x = acc30; ov.y = acc31;
            *(reinterpret_cast<float2*>(out + (size_t)(base + 3) * DIM) + lane) = ov;
        } else {
            if (base + 1 < N) { ov.x = acc10; ov.y = acc11;
                *(reinterpret_cast<float2*>(out + (size_t)(base + 1) * DIM) + lane) = ov; }
            if (base + 2 < N) { ov.x = acc20; ov.y = acc21;
                *(reinterpret_cast<float2*>(out + (size_t)(base + 2) * DIM) + lane) = ov; }
        }
        __syncwarp();   // protect stage before next iteration overwrites it
    }
}

// ---------------------------------------------------------------------------
extern "C" void kernel_launch(void* const* d_in, const int* in_sizes, int n_in,
                              void* d_out, int out_size) {
    // Map inputs by element count (robust to metadata ordering)
    const float* x    = nullptr;
    const void*  ei   = nullptr;
    const float* W    = nullptr;
    const float* b    = nullptr;
    const float* beta = nullptr;
    int x_sz = 0, ei_sz = 0;
    for (int i = 0; i < n_in; i++) {
        int s = in_sizes[i];
        if (s == 1)               beta = (const float*)d_in[i];
        else if (s == 64)         b    = (const float*)d_in[i];
        else if (s == 64 * 64)    W    = (const float*)d_in[i];
        else if (s == out_size)   { x  = (const float*)d_in[i]; x_sz = s; }
        else                      { ei = d_in[i]; ei_sz = s; }
    }
    float* out = (float*)d_out;

    const int N = x_sz / DIM;    // 50000
    const int E = ei_sz / 2;     // 800000

    init_kernel<<<(N + 255) / 256, 256>>>(ei, E, N);
    build_kernel<<<(E / 2 + 255) / 256, 256>>>(ei, E, N);
    {
        long long threads = (long long)N * 32;
        int blocks = (int)((threads + 255) / 256);
        agg_kernel<<<blocks, 256>>>(x, beta, N);
    }
    out_kernel<<<740, 256>>>(W, b, out, N);
}

// round 17
// speedup vs baseline: 1.3297x; 1.3297x over previous
#include <cuda_runtime.h>
#include <cstdint>

#define NNODES 50000
#define DIM 64
#define CAP 128          // per-node bucket capacity; deg ~ Binomial(8e5, 2e-5), mean 16
#define EPS_MSG 1e-7f
#define LOG2E 1.4426950408889634f

// Static scratch
__device__ int   g_cnt[NNODES];
__device__ int   g_slot[NNODES * CAP];   // per-node src lists (node indices)
__device__ float g_agg[NNODES * DIM];    // aggregated rows
__device__ int   g_is64;                 // edge_index dtype flag

// ---------------------------------------------------------------------------
// init: zero counters; warp 0 of block 0 probes edge_index dtype in parallel.
// int64 data: all values in [0,N). int32 read as int64: lo + hi*2^32, out of
// range unless hi==0 (~1/N per probe; 32 parallel probes => ~impossible).
// ---------------------------------------------------------------------------
__global__ void init_kernel(const void* __restrict__ ei, int E, int N) {
    int i = blockIdx.x * blockDim.x + threadIdx.x;
    if (i < N) g_cnt[i] = 0;
    if (blockIdx.x == 0 && threadIdx.x < 32) {
        const long long* p = (const long long*)ei;
        int probes = (2 * E < 32) ? 2 * E : 32;
        int bad = 0;
        if ((int)threadIdx.x < probes) {
            long long v = p[threadIdx.x];
            bad = (v < 0 || v >= (long long)N);
        }
        unsigned m = __ballot_sync(0xFFFFFFFFu, bad);
        if (threadIdx.x == 0) g_is64 = (m == 0u) ? 1 : 0;
    }
}

// ---------------------------------------------------------------------------
// bucket build: claim a slot in dst's list, record src. cnt = final degree.
// 2 edges per thread, vectorized index loads.
// ---------------------------------------------------------------------------
__global__ void build_kernel(const void* __restrict__ ei, int E, int N) {
    int t = blockIdx.x * blockDim.x + threadIdx.x;
    int e = t * 2;
    if (e >= E) return;
    int d0, s0, d1, s1;
    bool two = (e + 1 < E);
    if (g_is64) {
        const long long* p = (const long long*)ei;
        if (two) {
            longlong2 dv = __ldg(reinterpret_cast<const longlong2*>(p + e));
            longlong2 sv = __ldg(reinterpret_cast<const longlong2*>(p + (long long)E + e));
            d0 = (int)dv.x; d1 = (int)dv.y;
            s0 = (int)sv.x; s1 = (int)sv.y;
        } else {
            d0 = (int)p[e]; s0 = (int)p[(long long)E + e];
            d1 = -1; s1 = -1;
        }
    } else {
        const int* p = (const int*)ei;
        if (two) {
            int2 dv = __ldg(reinterpret_cast<const int2*>(p + e));
            int2 sv = __ldg(reinterpret_cast<const int2*>(p + E + e));
            d0 = dv.x; d1 = dv.y;
            s0 = sv.x; s1 = sv.y;
        } else {
            d0 = p[e]; s0 = p[E + e];
            d1 = -1; s1 = -1;
        }
    }
    if ((unsigned)d0 < (unsigned)N && (unsigned)s0 < (unsigned)N) {
        int pos = atomicAdd(&g_cnt[d0], 1);
        if (pos < CAP) g_slot[d0 * CAP + pos] = s0;
    }
    if (two && (unsigned)d1 < (unsigned)N && (unsigned)s1 < (unsigned)N) {
        int pos = atomicAdd(&g_cnt[d1], 1);
        if (pos < CAP) g_slot[d1 * CAP + pos] = s1;
    }
}

// ---------------------------------------------------------------------------
// aggregate: one warp per node (6250 blocks, no grid-stride, no smem), lane
// owns 2 channels. Exact algebra (eps + common exp factor cancel):
//   agg_c = (Σ r·exp2(bl·r)) / (Σ exp2(bl·r)) + eps,  r = relu(x), bl = β·log2e
// ---------------------------------------------------------------------------
__global__ void __launch_bounds__(256) agg_kernel(const float* __restrict__ x,
                                                  const float* __restrict__ beta,
                                                  int N) {
    int warp = (int)((blockIdx.x * blockDim.x + threadIdx.x) >> 5);
    int lane = threadIdx.x & 31;
    if (warp >= N) return;

    int deg = g_cnt[warp];
    if (deg > CAP) deg = CAP;
    const float bl = __ldg(beta) * LOG2E;
    const int* slots = g_slot + (size_t)warp * CAP;

    float d0 = 0.f, d1 = 0.f, n0 = 0.f, n1 = 0.f;

    int i = 0;
    for (; i + 4 <= deg; i += 4) {
        int4 s = __ldg(reinterpret_cast<const int4*>(slots + i));  // broadcast, aligned
        float2 va = __ldg(reinterpret_cast<const float2*>(x + (size_t)s.x * DIM) + lane);
        float2 vb = __ldg(reinterpret_cast<const float2*>(x + (size_t)s.y * DIM) + lane);
        float2 vc = __ldg(reinterpret_cast<const float2*>(x + (size_t)s.z * DIM) + lane);
        float2 vd = __ldg(reinterpret_cast<const float2*>(x + (size_t)s.w * DIM) + lane);

#define ACC2(v)                                                   \
        {                                                         \
            float r0 = fmaxf((v).x, 0.f), r1 = fmaxf((v).y, 0.f); \
            float t0 = exp2f(bl * r0),    t1 = exp2f(bl * r1);    \
            d0 += t0; d1 += t1;                                   \
            n0 = fmaf(r0, t0, n0); n1 = fmaf(r1, t1, n1);         \
        }
        ACC2(va) ACC2(vb) ACC2(vc) ACC2(vd)
    }
    for (; i < deg; i++) {
        int s0 = __ldg(slots + i);
        float2 v = __ldg(reinterpret_cast<const float2*>(x + (size_t)s0 * DIM) + lane);
        ACC2(v)
    }
#undef ACC2

    float2 o;
    if (deg > 0) {
        o.x = n0 / d0 + EPS_MSG;   // d>0 guaranteed: exp2 > 0
        o.y = n1 / d1 + EPS_MSG;
    } else {
        o.x = 0.f; o.y = 0.f;      // empty segment -> agg = 0 (matches reference)
    }
    *(reinterpret_cast<float2*>(g_agg + (size_t)warp * DIM) + lane) = o;
}

// ---------------------------------------------------------------------------
// out = agg @ W^T + b. Thread owns ONE output channel c with W row c in 16
// float4 REGISTERS (zero smem cost for W). Warp = 32 channels (half of DIM),
// processes 8 nodes per group: 8 coalesced LDG.64 -> smem stage -> inner loop
// is 8 broadcast LDS.128 (1 wavefront each) + 32 FMA per kq. Wavefronts per
// FMA drop 0.375 -> 0.25 vs R16; W regs filled once per block (L1-shared
// across the 4 warps of each half).
// ---------------------------------------------------------------------------
__global__ void __launch_bounds__(256) out_kernel(const float* __restrict__ W,
                                                  const float* __restrict__ b,
                                                  float* __restrict__ out,
                                                  int N) {
    __shared__ __align__(16) float stage[8][8][DIM];   // [warp][node][chan] = 16 KB

    const int wid  = threadIdx.x >> 5;
    const int lane = threadIdx.x & 31;
    const int h    = wid & 1;        // channel half: 0 -> c in [0,32), 1 -> [32,64)
    const int s    = wid >> 1;       // node-group stream 0..3
    const int c    = h * 32 + lane;  // this thread's output channel

    // W row c -> registers (one-time; warps of same half hit L1 after first)
    float4 wr[16];
#pragma unroll
    for (int kq = 0; kq < 16; kq++)
        wr[kq] = __ldg(reinterpret_cast<const float4*>(W + (size_t)c * DIM + 4 * kq));
    const float bc = __ldg(b + c);

    const int gstride = gridDim.x * 4 * 8;
    for (int base = (blockIdx.x * 4 + s) * 8; base < N; base += gstride) {
        const float2* g2 = reinterpret_cast<const float2*>(g_agg);
        const bool full = (base + 7 < N);   // N=50000 divisible by 8 -> always true

        // 8 coalesced row loads (float2 per lane), one batched wave (MLP=8)
        float2 t[8];
#pragma unroll
        for (int n = 0; n < 8; n++) {
            t[n] = (full || base + n < N)
                 ? __ldg(g2 + (size_t)(base + n) * 32 + lane)
                 : make_float2(0.f, 0.f);
        }
#pragma unroll
        for (int n = 0; n < 8; n++)
            *reinterpret_cast<float2*>(&stage[wid][n][2 * lane]) = t[n];
        __syncwarp();

        float acc[8];
#pragma unroll
        for (int n = 0; n < 8; n++) acc[n] = bc;

#pragma unroll
        for (int kq = 0; kq < 16; kq++) {
            const float4 w4 = wr[kq];
#pragma unroll
            for (int n = 0; n < 8; n++) {
                float4 a = *reinterpret_cast<const float4*>(&stage[wid][n][4 * kq]); // broadcast
                acc[n] = fmaf(a.x, w4.x, acc[n]);
                acc[n] = fmaf(a.y, w4.y, acc[n]);
                acc[n] = fmaf(a.z, w4.z, acc[n]);
                acc[n] = fmaf(a.w, w4.w, acc[n]);
            }
        }

#pragma unroll
        for (int n = 0; n < 8; n++) {
            if (full || base + n < N)
                out[(size_t)(base + n) * DIM + c] = acc[n];   // 32 consecutive floats/warp
        }
        __syncwarp();   // protect stage before next iteration overwrites it
    }
}

// ---------------------------------------------------------------------------
extern "C" void kernel_launch(void* const* d_in, const int* in_sizes, int n_in,
                              void* d_out, int out_size) {
    // Map inputs by element count (robust to metadata ordering)
    const float* x    = nullptr;
    const void*  ei   = nullptr;
    const float* W    = nullptr;
    const float* b    = nullptr;
    const float* beta = nullptr;
    int x_sz = 0, ei_sz = 0;
    for (int i = 0; i < n_in; i++) {
        int s = in_sizes[i];
        if (s == 1)               beta = (const float*)d_in[i];
        else if (s == 64)         b    = (const float*)d_in[i];
        else if (s == 64 * 64)    W    = (const float*)d_in[i];
        else if (s == out_size)   { x  = (const float*)d_in[i]; x_sz = s; }
        else                      { ei = d_in[i]; ei_sz = s; }
    }
    float* out = (float*)d_out;

    const int N = x_sz / DIM;    // 50000
    const int E = ei_sz / 2;     // 800000

    init_kernel<<<(N + 255) / 256, 256>>>(ei, E, N);
    build_kernel<<<(E / 2 + 255) / 256, 256>>>(ei, E, N);
    {
        long long threads = (long long)N * 32;
        int blocks = (int)((threads + 255) / 256);
        agg_kernel<<<blocks, 256>>>(x, beta, N);
    }
    out_kernel<<<592, 256>>>(W, b, out, N);
}